// round 2
// baseline (speedup 1.0000x reference)
#include <cuda_runtime.h>
#include <cuda_bf16.h>
#include <math.h>
#include <float.h>

// Problem constants
#define BATCH 32
#define LSEQ  2048
#define EDIM  1024
#define NHEAD 16
#define DHEAD 64
#define HD    (NHEAD * DHEAD)     // 1024
#define ROWS  (BATCH * LSEQ)      // 65536
#define FLAT  (LSEQ * EDIM)       // 2097152
#define NCLS  2

// ---------------------------------------------------------------------------
// Device-global scratch (allocation-free rule: static __device__ arrays)
// ---------------------------------------------------------------------------
__device__ float g_h[(size_t)ROWS * EDIM];     // 256 MB  h = embed[x]
__device__ float g_q[(size_t)ROWS * HD];       // 256 MB  q, later reused for att
__device__ float g_k[(size_t)ROWS * HD];       // 256 MB
__device__ float g_v[(size_t)ROWS * HD];       // 256 MB
__device__ float g_out[(size_t)ROWS * EDIM];   // 256 MB  out = h + att@Wo
__device__ double g_logits[BATCH * NCLS];      // 64 accumulators

// ---------------------------------------------------------------------------
// 1) Embedding gather: h[row, :] = embed_w[x[row], :]
// ---------------------------------------------------------------------------
__global__ __launch_bounds__(256) void gather_kernel(
    const int* __restrict__ x, const float* __restrict__ emb)
{
    int row = blockIdx.x;
    int v = x[row];
    const float4* src = (const float4*)(emb + (size_t)v * EDIM);
    float4* dst = (float4*)(g_h + (size_t)row * EDIM);
    dst[threadIdx.x] = src[threadIdx.x];   // 256 threads * float4 = 1024 floats
}

// ---------------------------------------------------------------------------
// 2) SGEMM: D = A[M,K] @ B[K,N] (+ Cin), row-major. 128x128 tile, 8x8/thread.
//    M=65536, N=1024, K=1024 always (divisible, no bounds checks).
// ---------------------------------------------------------------------------
__global__ __launch_bounds__(256) void sgemm_kernel(
    const float* __restrict__ A, const float* __restrict__ B,
    const float* __restrict__ Cin, float* __restrict__ D,
    int K, int ldb, int ldd)
{
    __shared__ float As[8][128];
    __shared__ float Bs[8][128];

    int t = threadIdx.x;
    int row0 = blockIdx.y * 128;
    int col0 = blockIdx.x * 128;

    // A tile loader: 128 rows x 8 cols; thread -> (row = t>>1, col = (t&1)*4)
    int ar = t >> 1, ac = (t & 1) << 2;
    // B tile loader: 8 rows x 128 cols; thread -> (row = t>>5, col = (t&31)*4)
    int br = t >> 5, bc = (t & 31) << 2;

    const float* Ap = A + (size_t)(row0 + ar) * K + ac;
    const float* Bp = B + (size_t)br * ldb + col0 + bc;

    int tx = (t & 15) << 3;   // output col within tile
    int ty = (t >> 4) << 3;   // output row within tile

    float acc[8][8];
#pragma unroll
    for (int i = 0; i < 8; i++)
#pragma unroll
        for (int j = 0; j < 8; j++) acc[i][j] = 0.f;

    for (int k0 = 0; k0 < K; k0 += 8) {
        float4 av = *(const float4*)(Ap + k0);
        float4 bv = *(const float4*)(Bp + (size_t)k0 * ldb);
        __syncthreads();
        As[ac + 0][ar] = av.x;
        As[ac + 1][ar] = av.y;
        As[ac + 2][ar] = av.z;
        As[ac + 3][ar] = av.w;
        *(float4*)&Bs[br][bc] = bv;
        __syncthreads();
#pragma unroll
        for (int kk = 0; kk < 8; kk++) {
            float a[8], b[8];
            *(float4*)(a)     = *(float4*)&As[kk][ty];
            *(float4*)(a + 4) = *(float4*)&As[kk][ty + 4];
            *(float4*)(b)     = *(float4*)&Bs[kk][tx];
            *(float4*)(b + 4) = *(float4*)&Bs[kk][tx + 4];
#pragma unroll
            for (int i = 0; i < 8; i++)
#pragma unroll
                for (int j = 0; j < 8; j++)
                    acc[i][j] += a[i] * b[j];
        }
    }

    // Epilogue (optional residual add)
#pragma unroll
    for (int i = 0; i < 8; i++) {
        size_t r = (size_t)(row0 + ty + i) * ldd + col0 + tx;
        if (Cin != nullptr) {
            const float* crow = Cin + r;
#pragma unroll
            for (int j = 0; j < 8; j++) acc[i][j] += crow[j];
        }
        *(float4*)(D + r)     = *(float4*)&acc[i][0];
        *(float4*)(D + r + 4) = *(float4*)&acc[i][4];
    }
}

// ---------------------------------------------------------------------------
// 3) Attention: per (l, n): scores[32x32] = q·k * scale over d=64;
//    softmax over j; att = prob @ v. Writes att in place into g_q.
// ---------------------------------------------------------------------------
__global__ __launch_bounds__(256) void attn_kernel()
{
    __shared__ float qs[32][64];
    __shared__ float ks[32][64];
    __shared__ float vs[32][64];
    __shared__ float sc[32][33];

    int l = blockIdx.x >> 4;     // 0..2047
    int n = blockIdx.x & 15;     // 0..15
    int t = threadIdx.x;

    int i  = t >> 3;             // 0..31  (batch index)
    int d0 = (t & 7) << 3;       // 0,8,...,56

    size_t base = (((size_t)i * LSEQ + l) * NHEAD + n) * DHEAD + d0;
    *(float4*)&qs[i][d0]     = *(const float4*)&g_q[base];
    *(float4*)&qs[i][d0 + 4] = *(const float4*)&g_q[base + 4];
    *(float4*)&ks[i][d0]     = *(const float4*)&g_k[base];
    *(float4*)&ks[i][d0 + 4] = *(const float4*)&g_k[base + 4];
    *(float4*)&vs[i][d0]     = *(const float4*)&g_v[base];
    *(float4*)&vs[i][d0 + 4] = *(const float4*)&g_v[base + 4];
    __syncthreads();

    const float scale = 0.125f;  // 1/sqrt(64)
    for (int p = t; p < 1024; p += 256) {
        int si = p >> 5, sj = p & 31;
        float dot = 0.f;
#pragma unroll
        for (int d = 0; d < 64; d++) dot += qs[si][d] * ks[sj][d];
        sc[si][sj] = dot * scale;
    }
    __syncthreads();

    if (t < 32) {
        float m = -FLT_MAX;
#pragma unroll
        for (int j = 0; j < 32; j++) m = fmaxf(m, sc[t][j]);
        float s = 0.f;
#pragma unroll
        for (int j = 0; j < 32; j++) { float e = __expf(sc[t][j] - m); sc[t][j] = e; s += e; }
        float inv = 1.f / s;
#pragma unroll
        for (int j = 0; j < 32; j++) sc[t][j] *= inv;
    }
    __syncthreads();

    float a[8] = {0,0,0,0,0,0,0,0};
#pragma unroll
    for (int j = 0; j < 32; j++) {
        float p = sc[i][j];
#pragma unroll
        for (int dd = 0; dd < 8; dd++) a[dd] += p * vs[j][d0 + dd];
    }
    *(float4*)&g_q[base]     = make_float4(a[0], a[1], a[2], a[3]);
    *(float4*)&g_q[base + 4] = make_float4(a[4], a[5], a[6], a[7]);
}

// ---------------------------------------------------------------------------
// 4) Logits: logits[b,c] = sum_i out[b,i] * Wf[i,c]  (i over 2.1M)
// ---------------------------------------------------------------------------
__global__ void zero_logits_kernel()
{
    if (threadIdx.x < BATCH * NCLS) g_logits[threadIdx.x] = 0.0;
}

__global__ __launch_bounds__(256) void logits_kernel(const float* __restrict__ Wf)
{
    const int CHUNK = 512;
    int i0 = blockIdx.x * CHUNK;
    int t = threadIdx.x;

    float acc[64];
#pragma unroll
    for (int k = 0; k < 64; k++) acc[k] = 0.f;

    for (int s = 0; s < CHUNK; s += 256) {
        int ii = i0 + s + t;
        float w0 = Wf[(size_t)ii * 2];
        float w1 = Wf[(size_t)ii * 2 + 1];
#pragma unroll
        for (int b = 0; b < 32; b++) {
            float v = g_out[(size_t)b * FLAT + ii];
            acc[2 * b]     += v * w0;
            acc[2 * b + 1] += v * w1;
        }
    }

    // warp reduce each of 64 accumulators
#pragma unroll
    for (int k = 0; k < 64; k++) {
        float v = acc[k];
        v += __shfl_down_sync(0xffffffffu, v, 16);
        v += __shfl_down_sync(0xffffffffu, v, 8);
        v += __shfl_down_sync(0xffffffffu, v, 4);
        v += __shfl_down_sync(0xffffffffu, v, 2);
        v += __shfl_down_sync(0xffffffffu, v, 1);
        acc[k] = v;
    }

    __shared__ float sacc[64];
    if (t < 64) sacc[t] = 0.f;
    __syncthreads();
    if ((t & 31) == 0) {
#pragma unroll
        for (int k = 0; k < 64; k++) atomicAdd(&sacc[k], acc[k]);
    }
    __syncthreads();
    if (t < 64) atomicAdd(&g_logits[t], (double)sacc[t]);
}

// ---------------------------------------------------------------------------
// 5) Loss: -mean_b ( logits[b, y[b]] - logsumexp_c(logits[b,:] + bf) )
// ---------------------------------------------------------------------------
__global__ void loss_kernel(const int* __restrict__ y,
                            const float* __restrict__ bf,
                            float* __restrict__ out)
{
    if (threadIdx.x != 0 || blockIdx.x != 0) return;
    double s = 0.0;
    double b0 = (double)bf[0], b1 = (double)bf[1];
    for (int b = 0; b < BATCH; b++) {
        double l0 = g_logits[2 * b]     + b0;
        double l1 = g_logits[2 * b + 1] + b1;
        double m  = l0 > l1 ? l0 : l1;
        double lse = m + log(exp(l0 - m) + exp(l1 - m));
        double lp  = (y[b] == 0 ? l0 : l1) - lse;
        s += lp;
    }
    out[0] = (float)(-s / (double)BATCH);
}

// ---------------------------------------------------------------------------
// Launch
// ---------------------------------------------------------------------------
extern "C" void kernel_launch(void* const* d_in, const int* in_sizes, int n_in,
                              void* d_out, int out_size)
{
    const int*   x     = (const int*)d_in[0];     // [32, 2048]
    const int*   y     = (const int*)d_in[1];     // [32]
    const float* emb   = (const float*)d_in[2];   // [100000, 1024]
    const float* Wq    = (const float*)d_in[3];   // [1024, 1024]
    const float* Wkv   = (const float*)d_in[4];   // [1024, 2048]
    const float* Wo    = (const float*)d_in[5];   // [1024, 1024]
    const float* Wf    = (const float*)d_in[6];   // [2097152, 2]
    const float* bf    = (const float*)d_in[7];   // [2]
    float* out = (float*)d_out;

    float *p_h, *p_q, *p_k, *p_v, *p_out;
    cudaGetSymbolAddress((void**)&p_h,   g_h);
    cudaGetSymbolAddress((void**)&p_q,   g_q);
    cudaGetSymbolAddress((void**)&p_k,   g_k);
    cudaGetSymbolAddress((void**)&p_v,   g_v);
    cudaGetSymbolAddress((void**)&p_out, g_out);

    // 1) gather
    gather_kernel<<<ROWS, 256>>>(x, emb);

    // 2) projections (all M=65536, N=1024, K=1024)
    dim3 ggrid(HD / 128, ROWS / 128);  // (8, 512)
    sgemm_kernel<<<ggrid, 256>>>(p_h, Wq,        nullptr, p_q, EDIM, HD,     HD);
    sgemm_kernel<<<ggrid, 256>>>(p_h, Wkv,       nullptr, p_k, EDIM, 2 * HD, HD);
    sgemm_kernel<<<ggrid, 256>>>(p_h, Wkv + HD,  nullptr, p_v, EDIM, 2 * HD, HD);

    // 3) attention (writes att in place into g_q)
    attn_kernel<<<LSEQ * NHEAD, 256>>>();

    // 4) out = h + att @ Wo
    sgemm_kernel<<<ggrid, 256>>>(p_q, Wo, p_h, p_out, HD, EDIM, EDIM);

    // 5) logits + loss
    zero_logits_kernel<<<1, 64>>>();
    logits_kernel<<<FLAT / 512, 256>>>(Wf);
    loss_kernel<<<1, 32>>>(y, bf, out);
}

// round 4
// speedup vs baseline: 4.8137x; 4.8137x over previous
#include <cuda_runtime.h>
#include <cuda_bf16.h>
#include <math.h>
#include <float.h>
#include <stdint.h>

// Problem constants
#define BATCH 32
#define LSEQ  2048
#define EDIM  1024
#define NHEAD 16
#define DHEAD 64
#define HD    (NHEAD * DHEAD)     // 1024
#define ROWS  (BATCH * LSEQ)      // 65536
#define FLAT  (LSEQ * EDIM)       // 2097152
#define NCLS  2

#define SMEM_SWIZZLE_128B(byte_offset) \
    ((byte_offset) ^ (((byte_offset) >> 3) & 0x70))

__device__ __forceinline__ uint32_t smem_to_u32(const void* smem_ptr) {
    uint32_t addr;
    asm("{ .reg .u64 tmp; cvta.to.shared.u64 tmp, %1; cvt.u32.u64 %0, tmp; }"
        : "=r"(addr) : "l"(smem_ptr));
    return addr;
}

__device__ __forceinline__ void cp_async16(uint32_t smem_addr, const void* gptr) {
    asm volatile("cp.async.cg.shared.global [%0], [%1], 16;"
                 :: "r"(smem_addr), "l"(gptr) : "memory");
}
__device__ __forceinline__ void cp_commit() {
    asm volatile("cp.async.commit_group;" ::: "memory");
}

__device__ __forceinline__ void ldmx4(uint32_t* r, uint32_t addr) {
    asm volatile("ldmatrix.sync.aligned.m8n8.x4.shared.b16 {%0,%1,%2,%3}, [%4];"
                 : "=r"(r[0]), "=r"(r[1]), "=r"(r[2]), "=r"(r[3]) : "r"(addr));
}

__device__ __forceinline__ void mma16816(float* c, const uint32_t* a, const uint32_t* b) {
    asm volatile(
        "mma.sync.aligned.m16n8k16.row.col.f32.bf16.bf16.f32 "
        "{%0,%1,%2,%3}, {%4,%5,%6,%7}, {%8,%9}, {%0,%1,%2,%3};"
        : "+f"(c[0]), "+f"(c[1]), "+f"(c[2]), "+f"(c[3])
        : "r"(a[0]), "r"(a[1]), "r"(a[2]), "r"(a[3]), "r"(b[0]), "r"(b[1]));
}

// ---------------------------------------------------------------------------
// Device-global scratch
// ---------------------------------------------------------------------------
__device__ __nv_bfloat16 g_hb[(size_t)ROWS * EDIM];   // 128 MB
__device__ __nv_bfloat16 g_qb[(size_t)ROWS * HD];     // q, then att (in place)
__device__ __nv_bfloat16 g_kb[(size_t)ROWS * HD];
__device__ __nv_bfloat16 g_vb[(size_t)ROWS * HD];
__device__ __nv_bfloat16 g_ob[(size_t)ROWS * EDIM];
__device__ __nv_bfloat16 g_wq[(size_t)HD * EDIM];     // Wq^T  [N, K]
__device__ __nv_bfloat16 g_wk[(size_t)HD * EDIM];
__device__ __nv_bfloat16 g_wv[(size_t)HD * EDIM];
__device__ __nv_bfloat16 g_wo[(size_t)EDIM * HD];
__device__ double g_logits[BATCH * NCLS];

// ---------------------------------------------------------------------------
// 1) Embedding gather -> bf16
// ---------------------------------------------------------------------------
__global__ __launch_bounds__(256) void gather_kernel(
    const int* __restrict__ x, const float* __restrict__ emb)
{
    int row = blockIdx.x;
    int v = x[row];
    int t = threadIdx.x;
    float4 f = ((const float4*)(emb + (size_t)v * EDIM))[t];
    __nv_bfloat162 lo = __floats2bfloat162_rn(f.x, f.y);
    __nv_bfloat162 hi = __floats2bfloat162_rn(f.z, f.w);
    uint2 p;
    p.x = *(uint32_t*)&lo;
    p.y = *(uint32_t*)&hi;
    ((uint2*)(g_hb + (size_t)row * EDIM))[t] = p;
}

// ---------------------------------------------------------------------------
// 1b) Weight transpose + convert: out[n, k] = in[k, coloff + n]  (bf16)
// ---------------------------------------------------------------------------
__global__ __launch_bounds__(256) void transpose_conv_kernel(
    const float* __restrict__ in, int ldin, int coloff,
    __nv_bfloat16* __restrict__ out)
{
    __shared__ float tile[32][33];
    int bx = blockIdx.x * 32;  // n block
    int by = blockIdx.y * 32;  // k block
    int tx = threadIdx.x & 31;
    int ty = threadIdx.x >> 5;
    for (int i = ty; i < 32; i += 8)
        tile[i][tx] = in[(size_t)(by + i) * ldin + coloff + bx + tx];
    __syncthreads();
    for (int i = ty; i < 32; i += 8)
        out[(size_t)(bx + i) * 1024 + by + tx] = __float2bfloat16(tile[tx][i]);
}

// ---------------------------------------------------------------------------
// 2) bf16 tensor-core GEMM via mma.sync (baseline PTX; no tcgen05 in this
//    harness — PTX target is sm_103 without the 'a' feature set).
//    D[M,1024] = A[M,1024] @ Bt[1024,1024]^T (+ residual).
//    CTA 128x128, warp 32x64, K-chunk 64, double-buffered cp.async.
// ---------------------------------------------------------------------------
#define MT 128
#define NT 128
#define KC 64
#define A_BYTES (MT * 128)          // 16 KB per chunk (128B rows)
#define B_BYTES (NT * 128)          // 16 KB
#define NCHUNKS (1024 / KC)         // 16
#define GEMM_SMEM (2 * (A_BYTES + B_BYTES) + 1024)

__device__ __forceinline__ void load_chunk(
    uint32_t abuf, uint32_t bbuf,
    const char* Abase, const char* Bbase, int c, int t)
{
#pragma unroll
    for (int i = 0; i < 4; i++) {
        int seg = t + 256 * i;
        int r = seg >> 3, s = seg & 7;
        uint32_t off = SMEM_SWIZZLE_128B((uint32_t)(r * 128 + s * 16));
        cp_async16(abuf + off, Abase + (size_t)r * 2048 + c * 128 + s * 16);
    }
#pragma unroll
    for (int i = 0; i < 4; i++) {
        int seg = t + 256 * i;
        int r = seg >> 3, s = seg & 7;
        uint32_t off = SMEM_SWIZZLE_128B((uint32_t)(r * 128 + s * 16));
        cp_async16(bbuf + off, Bbase + (size_t)r * 2048 + c * 128 + s * 16);
    }
}

template<bool RES>
__global__ __launch_bounds__(256) void gemm_bf16_kernel(
    const __nv_bfloat16* __restrict__ A,
    const __nv_bfloat16* __restrict__ Bt,
    const __nv_bfloat16* __restrict__ Res,
    __nv_bfloat16* __restrict__ D)
{
    extern __shared__ char smem[];
    uint32_t base = (smem_to_u32(smem) + 1023) & ~1023u;
    uint32_t a_sm[2] = { base,                       base + A_BYTES + B_BYTES };
    uint32_t b_sm[2] = { base + A_BYTES,             base + 2 * A_BYTES + B_BYTES };

    int t = threadIdx.x;
    int wid = t >> 5, lane = t & 31;
    int mwarp0 = (wid & 3) * 32;
    int nwarp0 = (wid >> 2) * 64;
    size_t row0 = (size_t)blockIdx.y * MT;
    int col0 = blockIdx.x * NT;

    const char* Abase = (const char*)(A + row0 * 1024);
    const char* Bbase = (const char*)(Bt + (size_t)col0 * 1024);

    // per-lane ldmatrix address components
    int g = lane & 7, sel = lane >> 3;
    int mA = mwarp0 + g + (sel & 1) * 8;
    uint32_t aRow[2] = { (uint32_t)(mA * 128), (uint32_t)((mA + 16) * 128) };
    uint32_t aKb = (uint32_t)((sel >> 1) * 16);
    uint32_t aX  = (uint32_t)((mA & 7) << 4);

    int nB = nwarp0 + g + ((sel >> 1) * 8);
    uint32_t bRow[4] = { (uint32_t)(nB * 128), (uint32_t)((nB + 16) * 128),
                         (uint32_t)((nB + 32) * 128), (uint32_t)((nB + 48) * 128) };
    uint32_t bKb = (uint32_t)((sel & 1) * 16);
    uint32_t bX  = (uint32_t)((nB & 7) << 4);

    float acc[2][8][4];
#pragma unroll
    for (int i = 0; i < 2; i++)
#pragma unroll
        for (int j = 0; j < 8; j++)
#pragma unroll
            for (int k = 0; k < 4; k++) acc[i][j][k] = 0.f;

    // prologue
    load_chunk(a_sm[0], b_sm[0], Abase, Bbase, 0, t);
    cp_commit();

    for (int c = 0; c < NCHUNKS; c++) {
        int buf = c & 1;
        if (c + 1 < NCHUNKS) {
            load_chunk(a_sm[buf ^ 1], b_sm[buf ^ 1], Abase, Bbase, c + 1, t);
            cp_commit();
            asm volatile("cp.async.wait_group 1;" ::: "memory");
        } else {
            asm volatile("cp.async.wait_group 0;" ::: "memory");
        }
        __syncthreads();

        uint32_t ab = a_sm[buf], bb = b_sm[buf];
#pragma unroll
        for (int s = 0; s < 4; s++) {         // 4 k16 steps per chunk
            uint32_t kb0 = (uint32_t)(s * 32);
            uint32_t afrag[2][4], bfrag[4][4];
#pragma unroll
            for (int mi = 0; mi < 2; mi++)
                ldmx4(afrag[mi], ab + aRow[mi] + ((aKb + kb0) ^ aX));
#pragma unroll
            for (int j = 0; j < 4; j++)
                ldmx4(bfrag[j], bb + bRow[j] + ((bKb + kb0) ^ bX));
#pragma unroll
            for (int mi = 0; mi < 2; mi++)
#pragma unroll
                for (int j = 0; j < 4; j++) {
                    mma16816(acc[mi][2 * j],     afrag[mi], &bfrag[j][0]);
                    mma16816(acc[mi][2 * j + 1], afrag[mi], &bfrag[j][2]);
                }
        }
        __syncthreads();
    }

    // Epilogue
#pragma unroll
    for (int mi = 0; mi < 2; mi++) {
        size_t r0 = row0 + mwarp0 + mi * 16 + (lane >> 2);
#pragma unroll
        for (int nj = 0; nj < 8; nj++) {
            int col = col0 + nwarp0 + nj * 8 + (lane & 3) * 2;
            float c0 = acc[mi][nj][0], c1 = acc[mi][nj][1];
            float c2 = acc[mi][nj][2], c3 = acc[mi][nj][3];
            if (RES) {
                uint32_t u0 = *(const uint32_t*)(Res + r0 * 1024 + col);
                uint32_t u1 = *(const uint32_t*)(Res + (r0 + 8) * 1024 + col);
                float2 f0 = __bfloat1622float2(*(__nv_bfloat162*)&u0);
                float2 f1 = __bfloat1622float2(*(__nv_bfloat162*)&u1);
                c0 += f0.x; c1 += f0.y; c2 += f1.x; c3 += f1.y;
            }
            __nv_bfloat162 h0 = __floats2bfloat162_rn(c0, c1);
            __nv_bfloat162 h1 = __floats2bfloat162_rn(c2, c3);
            *(uint32_t*)(D + r0 * 1024 + col)       = *(uint32_t*)&h0;
            *(uint32_t*)(D + (r0 + 8) * 1024 + col) = *(uint32_t*)&h1;
        }
    }
}

// ---------------------------------------------------------------------------
// 3) Attention (bf16 in/out, fp32 compute). Writes att in place into g_qb.
// ---------------------------------------------------------------------------
__device__ __forceinline__ void ld8_bf16(const __nv_bfloat16* p, float* dst)
{
    uint4 u = *(const uint4*)p;
    const __nv_bfloat162* h2 = (const __nv_bfloat162*)&u;
#pragma unroll
    for (int i = 0; i < 4; i++) {
        float2 f = __bfloat1622float2(h2[i]);
        dst[2 * i] = f.x; dst[2 * i + 1] = f.y;
    }
}

__global__ __launch_bounds__(256) void attn_kernel()
{
    __shared__ float qs[32][64];
    __shared__ float ks[32][64];
    __shared__ float vs[32][64];
    __shared__ float sc[32][33];

    int l = blockIdx.x >> 4;
    int n = blockIdx.x & 15;
    int t = threadIdx.x;

    int i  = t >> 3;
    int d0 = (t & 7) << 3;

    size_t base = (((size_t)i * LSEQ + l) * NHEAD + n) * DHEAD + d0;
    ld8_bf16(&g_qb[base], &qs[i][d0]);
    ld8_bf16(&g_kb[base], &ks[i][d0]);
    ld8_bf16(&g_vb[base], &vs[i][d0]);
    __syncthreads();

    const float scale = 0.125f;
    for (int p = t; p < 1024; p += 256) {
        int si = p >> 5, sj = p & 31;
        float dot = 0.f;
#pragma unroll
        for (int d = 0; d < 64; d++) dot += qs[si][d] * ks[sj][d];
        sc[si][sj] = dot * scale;
    }
    __syncthreads();

    if (t < 32) {
        float m = -FLT_MAX;
#pragma unroll
        for (int j = 0; j < 32; j++) m = fmaxf(m, sc[t][j]);
        float s = 0.f;
#pragma unroll
        for (int j = 0; j < 32; j++) { float e = __expf(sc[t][j] - m); sc[t][j] = e; s += e; }
        float inv = 1.f / s;
#pragma unroll
        for (int j = 0; j < 32; j++) sc[t][j] *= inv;
    }
    __syncthreads();

    float a[8] = {0,0,0,0,0,0,0,0};
#pragma unroll
    for (int j = 0; j < 32; j++) {
        float p = sc[i][j];
#pragma unroll
        for (int dd = 0; dd < 8; dd++) a[dd] += p * vs[j][d0 + dd];
    }
    uint4 outv;
    uint32_t* pk = (uint32_t*)&outv;
#pragma unroll
    for (int p = 0; p < 4; p++) {
        __nv_bfloat162 h2 = __floats2bfloat162_rn(a[2 * p], a[2 * p + 1]);
        pk[p] = *(uint32_t*)&h2;
    }
    *(uint4*)&g_qb[base] = outv;
}

// ---------------------------------------------------------------------------
// 4) Logits
// ---------------------------------------------------------------------------
__global__ void zero_logits_kernel()
{
    if (threadIdx.x < BATCH * NCLS) g_logits[threadIdx.x] = 0.0;
}

__global__ __launch_bounds__(256) void logits_kernel(const float* __restrict__ Wf)
{
    const int CHUNK = 512;
    int i0 = blockIdx.x * CHUNK;
    int t = threadIdx.x;

    float acc[64];
#pragma unroll
    for (int k = 0; k < 64; k++) acc[k] = 0.f;

    for (int s = 0; s < CHUNK; s += 256) {
        int ii = i0 + s + t;
        float w0 = Wf[(size_t)ii * 2];
        float w1 = Wf[(size_t)ii * 2 + 1];
#pragma unroll
        for (int b = 0; b < 32; b++) {
            float v = __bfloat162float(g_ob[(size_t)b * FLAT + ii]);
            acc[2 * b]     += v * w0;
            acc[2 * b + 1] += v * w1;
        }
    }

#pragma unroll
    for (int k = 0; k < 64; k++) {
        float v = acc[k];
        v += __shfl_down_sync(0xffffffffu, v, 16);
        v += __shfl_down_sync(0xffffffffu, v, 8);
        v += __shfl_down_sync(0xffffffffu, v, 4);
        v += __shfl_down_sync(0xffffffffu, v, 2);
        v += __shfl_down_sync(0xffffffffu, v, 1);
        acc[k] = v;
    }

    __shared__ float sacc[64];
    if (t < 64) sacc[t] = 0.f;
    __syncthreads();
    if ((t & 31) == 0) {
#pragma unroll
        for (int k = 0; k < 64; k++) atomicAdd(&sacc[k], acc[k]);
    }
    __syncthreads();
    if (t < 64) atomicAdd(&g_logits[t], (double)sacc[t]);
}

// ---------------------------------------------------------------------------
// 5) Loss
// ---------------------------------------------------------------------------
__global__ void loss_kernel(const int* __restrict__ y,
                            const float* __restrict__ bf,
                            float* __restrict__ out)
{
    if (threadIdx.x != 0 || blockIdx.x != 0) return;
    double s = 0.0;
    double b0 = (double)bf[0], b1 = (double)bf[1];
    for (int b = 0; b < BATCH; b++) {
        double l0 = g_logits[2 * b]     + b0;
        double l1 = g_logits[2 * b + 1] + b1;
        double m  = l0 > l1 ? l0 : l1;
        double lse = m + log(exp(l0 - m) + exp(l1 - m));
        double lp  = (y[b] == 0 ? l0 : l1) - lse;
        s += lp;
    }
    out[0] = (float)(-s / (double)BATCH);
}

// ---------------------------------------------------------------------------
// Launch
// ---------------------------------------------------------------------------
extern "C" void kernel_launch(void* const* d_in, const int* in_sizes, int n_in,
                              void* d_out, int out_size)
{
    const int*   x     = (const int*)d_in[0];
    const int*   y     = (const int*)d_in[1];
    const float* emb   = (const float*)d_in[2];
    const float* Wq    = (const float*)d_in[3];
    const float* Wkv   = (const float*)d_in[4];
    const float* Wo    = (const float*)d_in[5];
    const float* Wf    = (const float*)d_in[6];
    const float* bf    = (const float*)d_in[7];
    float* out = (float*)d_out;

    __nv_bfloat16 *p_hb, *p_qb, *p_kb, *p_vb, *p_ob, *p_wq, *p_wk, *p_wv, *p_wo;
    cudaGetSymbolAddress((void**)&p_hb, g_hb);
    cudaGetSymbolAddress((void**)&p_qb, g_qb);
    cudaGetSymbolAddress((void**)&p_kb, g_kb);
    cudaGetSymbolAddress((void**)&p_vb, g_vb);
    cudaGetSymbolAddress((void**)&p_ob, g_ob);
    cudaGetSymbolAddress((void**)&p_wq, g_wq);
    cudaGetSymbolAddress((void**)&p_wk, g_wk);
    cudaGetSymbolAddress((void**)&p_wv, g_wv);
    cudaGetSymbolAddress((void**)&p_wo, g_wo);

    cudaFuncSetAttribute(gemm_bf16_kernel<false>,
                         cudaFuncAttributeMaxDynamicSharedMemorySize, GEMM_SMEM);
    cudaFuncSetAttribute(gemm_bf16_kernel<true>,
                         cudaFuncAttributeMaxDynamicSharedMemorySize, GEMM_SMEM);

    // 1) gather + weight prep
    gather_kernel<<<ROWS, 256>>>(x, emb);
    dim3 tgrid(32, 32), tblk(256);
    transpose_conv_kernel<<<tgrid, tblk>>>(Wq,  HD,     0,  p_wq);
    transpose_conv_kernel<<<tgrid, tblk>>>(Wkv, 2 * HD, 0,  p_wk);
    transpose_conv_kernel<<<tgrid, tblk>>>(Wkv, 2 * HD, HD, p_wv);
    transpose_conv_kernel<<<tgrid, tblk>>>(Wo,  EDIM,   0,  p_wo);

    // 2) projections (tensor cores via mma.sync)
    dim3 ggrid(EDIM / NT, ROWS / MT);  // (8, 512)
    gemm_bf16_kernel<false><<<ggrid, 256, GEMM_SMEM>>>(p_hb, p_wq, nullptr, p_qb);
    gemm_bf16_kernel<false><<<ggrid, 256, GEMM_SMEM>>>(p_hb, p_wk, nullptr, p_kb);
    gemm_bf16_kernel<false><<<ggrid, 256, GEMM_SMEM>>>(p_hb, p_wv, nullptr, p_vb);

    // 3) attention (in place: g_qb <- att)
    attn_kernel<<<LSEQ * NHEAD, 256>>>();

    // 4) out = h + att @ Wo
    gemm_bf16_kernel<true><<<ggrid, 256, GEMM_SMEM>>>(p_qb, p_wo, p_hb, p_ob);

    // 5) logits + loss
    zero_logits_kernel<<<1, 64>>>();
    logits_kernel<<<FLAT / 512, 256>>>(Wf);
    loss_kernel<<<1, 32>>>(y, bf, out);
}

// round 5
// speedup vs baseline: 8.2231x; 1.7083x over previous
#include <cuda_runtime.h>
#include <cuda_bf16.h>
#include <math.h>
#include <float.h>
#include <stdint.h>

// Problem constants
#define BATCH 32
#define LSEQ  2048
#define EDIM  1024
#define NHEAD 16
#define DHEAD 64
#define HD    (NHEAD * DHEAD)     // 1024
#define ROWS  (BATCH * LSEQ)      // 65536
#define FLAT  (LSEQ * EDIM)       // 2097152
#define NCLS  2

#define SMEM_SWIZZLE_128B(byte_offset) \
    ((byte_offset) ^ (((byte_offset) >> 3) & 0x70))

__device__ __forceinline__ uint32_t smem_to_u32(const void* smem_ptr) {
    uint32_t addr;
    asm("{ .reg .u64 tmp; cvta.to.shared.u64 tmp, %1; cvt.u32.u64 %0, tmp; }"
        : "=r"(addr) : "l"(smem_ptr));
    return addr;
}

__device__ __forceinline__ void cp_async16(uint32_t smem_addr, const void* gptr) {
    asm volatile("cp.async.cg.shared.global [%0], [%1], 16;"
                 :: "r"(smem_addr), "l"(gptr) : "memory");
}
__device__ __forceinline__ void cp_commit() {
    asm volatile("cp.async.commit_group;" ::: "memory");
}

__device__ __forceinline__ void ldmx4(uint32_t* r, uint32_t addr) {
    asm volatile("ldmatrix.sync.aligned.m8n8.x4.shared.b16 {%0,%1,%2,%3}, [%4];"
                 : "=r"(r[0]), "=r"(r[1]), "=r"(r[2]), "=r"(r[3]) : "r"(addr));
}
__device__ __forceinline__ void ldmx4t(uint32_t* r, uint32_t addr) {
    asm volatile("ldmatrix.sync.aligned.m8n8.x4.trans.shared.b16 {%0,%1,%2,%3}, [%4];"
                 : "=r"(r[0]), "=r"(r[1]), "=r"(r[2]), "=r"(r[3]) : "r"(addr));
}

__device__ __forceinline__ void mma16816(float* c, const uint32_t* a, const uint32_t* b) {
    asm volatile(
        "mma.sync.aligned.m16n8k16.row.col.f32.bf16.bf16.f32 "
        "{%0,%1,%2,%3}, {%4,%5,%6,%7}, {%8,%9}, {%0,%1,%2,%3};"
        : "+f"(c[0]), "+f"(c[1]), "+f"(c[2]), "+f"(c[3])
        : "r"(a[0]), "r"(a[1]), "r"(a[2]), "r"(a[3]), "r"(b[0]), "r"(b[1]));
}

// ---------------------------------------------------------------------------
// Device-global scratch
// ---------------------------------------------------------------------------
__device__ __nv_bfloat16 g_hb[(size_t)ROWS * EDIM];     // 128 MB
__device__ __nv_bfloat16 g_qb[(size_t)ROWS * HD];       // q, then att (in place)
__device__ __nv_bfloat16 g_kb[(size_t)ROWS * HD];
__device__ __nv_bfloat16 g_vb[(size_t)ROWS * HD];
__device__ __nv_bfloat16 g_ob[(size_t)ROWS * EDIM];
__device__ __nv_bfloat16 g_wqkv[(size_t)3 * HD * EDIM]; // [3072, 1024] fused Wq^T|Wk^T|Wv^T
__device__ __nv_bfloat16 g_wo[(size_t)EDIM * HD];
__device__ double g_logits[BATCH * NCLS];

// ---------------------------------------------------------------------------
// 1) Embedding gather -> bf16
// ---------------------------------------------------------------------------
__global__ __launch_bounds__(256) void gather_kernel(
    const int* __restrict__ x, const float* __restrict__ emb)
{
    int row = blockIdx.x;
    int v = x[row];
    int t = threadIdx.x;
    float4 f = ((const float4*)(emb + (size_t)v * EDIM))[t];
    __nv_bfloat162 lo = __floats2bfloat162_rn(f.x, f.y);
    __nv_bfloat162 hi = __floats2bfloat162_rn(f.z, f.w);
    uint2 p;
    p.x = *(uint32_t*)&lo;
    p.y = *(uint32_t*)&hi;
    ((uint2*)(g_hb + (size_t)row * EDIM))[t] = p;
}

// ---------------------------------------------------------------------------
// 1b) Weight transpose + convert: out[n, k] = in[k, coloff + n]  (bf16)
// ---------------------------------------------------------------------------
__global__ __launch_bounds__(256) void transpose_conv_kernel(
    const float* __restrict__ in, int ldin, int coloff,
    __nv_bfloat16* __restrict__ out)
{
    __shared__ float tile[32][33];
    int bx = blockIdx.x * 32;  // n block
    int by = blockIdx.y * 32;  // k block
    int tx = threadIdx.x & 31;
    int ty = threadIdx.x >> 5;
    for (int i = ty; i < 32; i += 8)
        tile[i][tx] = in[(size_t)(by + i) * ldin + coloff + bx + tx];
    __syncthreads();
    for (int i = ty; i < 32; i += 8)
        out[(size_t)(bx + i) * 1024 + by + tx] = __float2bfloat16(tile[tx][i]);
}

// ---------------------------------------------------------------------------
// 2) bf16 tensor-core GEMM (mma.sync; tcgen05 PTX is rejected by the
//    harness's .target sm_103). 3-stage cp.async pipeline, 1 sync/chunk.
//    D[M,*] = A[M,1024] @ Bt[N,1024]^T (+ residual). Output buffer selected
//    by global column block (fused QKV support).
// ---------------------------------------------------------------------------
#define MT 128
#define NT 128
#define A_BYTES (MT * 128)          // 16 KB per chunk (K-chunk 64)
#define B_BYTES (NT * 128)          // 16 KB
#define NCHUNKS 16
#define STAGES 3
#define GEMM_SMEM (STAGES * (A_BYTES + B_BYTES) + 1024)

__device__ __forceinline__ void load_chunk(
    uint32_t abuf, uint32_t bbuf,
    const char* Abase, const char* Bbase, int c, int t)
{
#pragma unroll
    for (int i = 0; i < 4; i++) {
        int seg = t + 256 * i;
        int r = seg >> 3, s = seg & 7;
        uint32_t off = SMEM_SWIZZLE_128B((uint32_t)(r * 128 + s * 16));
        cp_async16(abuf + off, Abase + (size_t)r * 2048 + c * 128 + s * 16);
    }
#pragma unroll
    for (int i = 0; i < 4; i++) {
        int seg = t + 256 * i;
        int r = seg >> 3, s = seg & 7;
        uint32_t off = SMEM_SWIZZLE_128B((uint32_t)(r * 128 + s * 16));
        cp_async16(bbuf + off, Bbase + (size_t)r * 2048 + c * 128 + s * 16);
    }
}

template<bool RES>
__global__ __launch_bounds__(256, 2) void gemm_bf16_kernel(
    const __nv_bfloat16* __restrict__ A,
    const __nv_bfloat16* __restrict__ Bt,
    const __nv_bfloat16* __restrict__ Res,
    __nv_bfloat16* __restrict__ D0,
    __nv_bfloat16* __restrict__ D1,
    __nv_bfloat16* __restrict__ D2)
{
    extern __shared__ char smem[];
    uint32_t base = (smem_to_u32(smem) + 1023) & ~1023u;
    uint32_t a_sm[STAGES], b_sm[STAGES];
#pragma unroll
    for (int s = 0; s < STAGES; s++) {
        a_sm[s] = base + s * (A_BYTES + B_BYTES);
        b_sm[s] = a_sm[s] + A_BYTES;
    }

    int t = threadIdx.x;
    int wid = t >> 5, lane = t & 31;
    int mwarp0 = (wid & 3) * 32;
    int nwarp0 = (wid >> 2) * 64;
    size_t row0 = (size_t)blockIdx.y * MT;
    int col0 = blockIdx.x * NT;

    // output buffer selection (fused QKV)
    int tgt = col0 >> 10;
    int colc = col0 & 1023;
    __nv_bfloat16* D = (tgt == 0) ? D0 : ((tgt == 1) ? D1 : D2);

    const char* Abase = (const char*)(A + row0 * 1024);
    const char* Bbase = (const char*)(Bt + (size_t)col0 * 1024);

    // per-lane ldmatrix address components
    int g = lane & 7, sel = lane >> 3;
    int mA = mwarp0 + g + (sel & 1) * 8;
    uint32_t aRow[2] = { (uint32_t)(mA * 128), (uint32_t)((mA + 16) * 128) };
    uint32_t aKb = (uint32_t)((sel >> 1) * 16);
    uint32_t aX  = (uint32_t)((mA & 7) << 4);

    int nB = nwarp0 + g + ((sel >> 1) * 8);
    uint32_t bRow[4] = { (uint32_t)(nB * 128), (uint32_t)((nB + 16) * 128),
                         (uint32_t)((nB + 32) * 128), (uint32_t)((nB + 48) * 128) };
    uint32_t bKb = (uint32_t)((sel & 1) * 16);
    uint32_t bX  = (uint32_t)((nB & 7) << 4);

    float acc[2][8][4];
#pragma unroll
    for (int i = 0; i < 2; i++)
#pragma unroll
        for (int j = 0; j < 8; j++)
#pragma unroll
            for (int k = 0; k < 4; k++) acc[i][j][k] = 0.f;

    // prologue: prime 2 stages
    load_chunk(a_sm[0], b_sm[0], Abase, Bbase, 0, t);
    cp_commit();
    load_chunk(a_sm[1], b_sm[1], Abase, Bbase, 1, t);
    cp_commit();

    int stage = 0;
    for (int c = 0; c < NCHUNKS; c++) {
        if (c < NCHUNKS - 1) {
            asm volatile("cp.async.wait_group 1;" ::: "memory");
        } else {
            asm volatile("cp.async.wait_group 0;" ::: "memory");
        }
        __syncthreads();
        if (c + 2 < NCHUNKS) {
            int ns = stage + 2; if (ns >= STAGES) ns -= STAGES;
            load_chunk(a_sm[ns], b_sm[ns], Abase, Bbase, c + 2, t);
            cp_commit();
        }

        uint32_t ab = a_sm[stage], bb = b_sm[stage];
#pragma unroll
        for (int s = 0; s < 4; s++) {         // 4 k16 steps per chunk
            uint32_t kb0 = (uint32_t)(s * 32);
            uint32_t afrag[2][4], bfrag[4][4];
#pragma unroll
            for (int mi = 0; mi < 2; mi++)
                ldmx4(afrag[mi], ab + aRow[mi] + ((aKb + kb0) ^ aX));
#pragma unroll
            for (int j = 0; j < 4; j++)
                ldmx4(bfrag[j], bb + bRow[j] + ((bKb + kb0) ^ bX));
#pragma unroll
            for (int mi = 0; mi < 2; mi++)
#pragma unroll
                for (int j = 0; j < 4; j++) {
                    mma16816(acc[mi][2 * j],     afrag[mi], &bfrag[j][0]);
                    mma16816(acc[mi][2 * j + 1], afrag[mi], &bfrag[j][2]);
                }
        }
        stage++; if (stage >= STAGES) stage -= STAGES;
    }

    // Epilogue
#pragma unroll
    for (int mi = 0; mi < 2; mi++) {
        size_t r0 = row0 + mwarp0 + mi * 16 + (lane >> 2);
#pragma unroll
        for (int nj = 0; nj < 8; nj++) {
            int col = colc + nwarp0 + nj * 8 + (lane & 3) * 2;
            float c0 = acc[mi][nj][0], c1 = acc[mi][nj][1];
            float c2 = acc[mi][nj][2], c3 = acc[mi][nj][3];
            if (RES) {
                uint32_t u0 = *(const uint32_t*)(Res + r0 * 1024 + col);
                uint32_t u1 = *(const uint32_t*)(Res + (r0 + 8) * 1024 + col);
                float2 f0 = __bfloat1622float2(*(__nv_bfloat162*)&u0);
                float2 f1 = __bfloat1622float2(*(__nv_bfloat162*)&u1);
                c0 += f0.x; c1 += f0.y; c2 += f1.x; c3 += f1.y;
            }
            __nv_bfloat162 h0 = __floats2bfloat162_rn(c0, c1);
            __nv_bfloat162 h1 = __floats2bfloat162_rn(c2, c3);
            *(uint32_t*)(D + r0 * 1024 + col)       = *(uint32_t*)&h0;
            *(uint32_t*)(D + (r0 + 8) * 1024 + col) = *(uint32_t*)&h1;
        }
    }
}

// ---------------------------------------------------------------------------
// 3) Attention on tensor cores. One warp per (l, n) pair:
//    S = Q K^T (mma), register softmax (shfl over quad), att = P V (mma,
//    P as register bf16 A-fragments, V via ldmatrix.trans).
//    Writes att in place into g_qb.
// ---------------------------------------------------------------------------
#define ATT_WARPS 8
#define ATT_SMEM (ATT_WARPS * 3 * 4096)   // 96 KB
#define ROWSTRIDE_B (LSEQ * NHEAD * DHEAD * 2)  // 4 MB: batch-row stride in bytes

__global__ __launch_bounds__(256) void attn_kernel()
{
    extern __shared__ char asmem[];
    int t = threadIdx.x, w = t >> 5, lane = t & 31;
    uint32_t wbase = smem_to_u32(asmem) + w * 12288;
    uint32_t qsm = wbase, ksm = wbase + 4096, vsm = wbase + 8192;

    int pair = blockIdx.x * ATT_WARPS + w;
    int l = pair >> 4, n = pair & 15;
    size_t ebase = ((size_t)l * NHEAD + n) * DHEAD;   // element offset at batch 0
    const char* qg = (const char*)(g_qb + ebase);
    const char* kg = (const char*)(g_kb + ebase);
    const char* vg = (const char*)(g_vb + ebase);

    // load Q/K/V tiles [32 rows(batch) x 64 bf16] into swizzled smem
#pragma unroll
    for (int i = 0; i < 8; i++) {
        int s = lane + 32 * i;
        int row = s >> 3, sub = s & 7;
        size_t go = (size_t)row * ROWSTRIDE_B + sub * 16;
        uint32_t so = SMEM_SWIZZLE_128B((uint32_t)(row * 128 + sub * 16));
        cp_async16(qsm + so, qg + go);
        cp_async16(ksm + so, kg + go);
        cp_async16(vsm + so, vg + go);
    }
    cp_commit();
    asm volatile("cp.async.wait_group 0;" ::: "memory");
    __syncwarp();

    int g8 = lane & 7, sel = lane >> 3;

    // ---- S = Q K^T  (scores 32x32, fp32 frags) ----
    float c[2][4][4];
#pragma unroll
    for (int mi = 0; mi < 2; mi++)
#pragma unroll
        for (int j = 0; j < 4; j++)
#pragma unroll
            for (int k = 0; k < 4; k++) c[mi][j][k] = 0.f;

#pragma unroll
    for (int kc = 0; kc < 4; kc++) {
        uint32_t kb = kc * 32;
        uint32_t af[2][4], bfr[2][4];
#pragma unroll
        for (int mi = 0; mi < 2; mi++) {
            int row = mi * 16 + g8 + (sel & 1) * 8;
            uint32_t off = row * 128 + ((kb + (sel >> 1) * 16) ^ ((row & 7) << 4));
            ldmx4(af[mi], qsm + off);
        }
#pragma unroll
        for (int nj2 = 0; nj2 < 2; nj2++) {
            int row = nj2 * 16 + g8 + (sel >> 1) * 8;
            uint32_t off = row * 128 + ((kb + (sel & 1) * 16) ^ ((row & 7) << 4));
            ldmx4(bfr[nj2], ksm + off);
        }
#pragma unroll
        for (int mi = 0; mi < 2; mi++)
#pragma unroll
            for (int nj2 = 0; nj2 < 2; nj2++) {
                mma16816(c[mi][2 * nj2],     af[mi], &bfr[nj2][0]);
                mma16816(c[mi][2 * nj2 + 1], af[mi], &bfr[nj2][2]);
            }
    }

    // ---- softmax over j (cols), rows r=lane>>2 (+8), per mi ----
    float inv0[2], inv1[2];
#pragma unroll
    for (int mi = 0; mi < 2; mi++) {
        float m0 = -FLT_MAX, m1 = -FLT_MAX;
#pragma unroll
        for (int j = 0; j < 4; j++) {
#pragma unroll
            for (int k = 0; k < 4; k++) c[mi][j][k] *= 0.125f;
            m0 = fmaxf(m0, fmaxf(c[mi][j][0], c[mi][j][1]));
            m1 = fmaxf(m1, fmaxf(c[mi][j][2], c[mi][j][3]));
        }
        m0 = fmaxf(m0, __shfl_xor_sync(0xffffffffu, m0, 1));
        m0 = fmaxf(m0, __shfl_xor_sync(0xffffffffu, m0, 2));
        m1 = fmaxf(m1, __shfl_xor_sync(0xffffffffu, m1, 1));
        m1 = fmaxf(m1, __shfl_xor_sync(0xffffffffu, m1, 2));
        float s0 = 0.f, s1 = 0.f;
#pragma unroll
        for (int j = 0; j < 4; j++) {
            c[mi][j][0] = __expf(c[mi][j][0] - m0);
            c[mi][j][1] = __expf(c[mi][j][1] - m0);
            c[mi][j][2] = __expf(c[mi][j][2] - m1);
            c[mi][j][3] = __expf(c[mi][j][3] - m1);
            s0 += c[mi][j][0] + c[mi][j][1];
            s1 += c[mi][j][2] + c[mi][j][3];
        }
        s0 += __shfl_xor_sync(0xffffffffu, s0, 1);
        s0 += __shfl_xor_sync(0xffffffffu, s0, 2);
        s1 += __shfl_xor_sync(0xffffffffu, s1, 1);
        s1 += __shfl_xor_sync(0xffffffffu, s1, 2);
        inv0[mi] = 1.f / s0;
        inv1[mi] = 1.f / s1;
    }

    // ---- pack P (unnormalized e) to bf16 A-fragments: pf[mi][kc][4] ----
    uint32_t pf[2][2][4];
#pragma unroll
    for (int mi = 0; mi < 2; mi++)
#pragma unroll
        for (int kc = 0; kc < 2; kc++) {
            __nv_bfloat162 x0 = __floats2bfloat162_rn(c[mi][2 * kc][0],     c[mi][2 * kc][1]);
            __nv_bfloat162 x1 = __floats2bfloat162_rn(c[mi][2 * kc][2],     c[mi][2 * kc][3]);
            __nv_bfloat162 x2 = __floats2bfloat162_rn(c[mi][2 * kc + 1][0], c[mi][2 * kc + 1][1]);
            __nv_bfloat162 x3 = __floats2bfloat162_rn(c[mi][2 * kc + 1][2], c[mi][2 * kc + 1][3]);
            pf[mi][kc][0] = *(uint32_t*)&x0;
            pf[mi][kc][1] = *(uint32_t*)&x1;
            pf[mi][kc][2] = *(uint32_t*)&x2;
            pf[mi][kc][3] = *(uint32_t*)&x3;
        }

    // ---- att = P V  (V via ldmatrix.trans) ----
    float cv[2][8][4];
#pragma unroll
    for (int mi = 0; mi < 2; mi++)
#pragma unroll
        for (int j = 0; j < 8; j++)
#pragma unroll
            for (int k = 0; k < 4; k++) cv[mi][j][k] = 0.f;

#pragma unroll
    for (int kc = 0; kc < 2; kc++) {
#pragma unroll
        for (int dj2 = 0; dj2 < 4; dj2++) {
            int row = kc * 16 + g8 + (sel & 1) * 8;
            uint32_t colb = dj2 * 32 + (sel >> 1) * 16;
            uint32_t off = row * 128 + (colb ^ ((row & 7) << 4));
            uint32_t bv[4];
            ldmx4t(bv, vsm + off);
#pragma unroll
            for (int mi = 0; mi < 2; mi++) {
                mma16816(cv[mi][2 * dj2],     pf[mi][kc], &bv[0]);
                mma16816(cv[mi][2 * dj2 + 1], pf[mi][kc], &bv[2]);
            }
        }
    }

    // ---- normalize + store (in place into g_qb) ----
    int r = lane >> 2, cq = (lane & 3) * 2;
#pragma unroll
    for (int mi = 0; mi < 2; mi++) {
        int i0 = mi * 16 + r;
        __nv_bfloat16* o0 = g_qb + ebase + (size_t)i0 * (LSEQ * NHEAD * DHEAD);
        __nv_bfloat16* o1 = o0 + (size_t)8 * (LSEQ * NHEAD * DHEAD);
#pragma unroll
        for (int dj = 0; dj < 8; dj++) {
            int col = dj * 8 + cq;
            __nv_bfloat162 h0 = __floats2bfloat162_rn(cv[mi][dj][0] * inv0[mi],
                                                      cv[mi][dj][1] * inv0[mi]);
            __nv_bfloat162 h1 = __floats2bfloat162_rn(cv[mi][dj][2] * inv1[mi],
                                                      cv[mi][dj][3] * inv1[mi]);
            *(uint32_t*)(o0 + col) = *(uint32_t*)&h0;
            *(uint32_t*)(o1 + col) = *(uint32_t*)&h1;
        }
    }
}

// ---------------------------------------------------------------------------
// 4) Logits
// ---------------------------------------------------------------------------
__global__ void zero_logits_kernel()
{
    if (threadIdx.x < BATCH * NCLS) g_logits[threadIdx.x] = 0.0;
}

__global__ __launch_bounds__(256) void logits_kernel(const float* __restrict__ Wf)
{
    const int CHUNK = 512;
    int i0 = blockIdx.x * CHUNK;
    int t = threadIdx.x;

    float acc[64];
#pragma unroll
    for (int k = 0; k < 64; k++) acc[k] = 0.f;

    for (int s = 0; s < CHUNK; s += 256) {
        int ii = i0 + s + t;
        float w0 = Wf[(size_t)ii * 2];
        float w1 = Wf[(size_t)ii * 2 + 1];
#pragma unroll
        for (int b = 0; b < 32; b++) {
            float v = __bfloat162float(g_ob[(size_t)b * FLAT + ii]);
            acc[2 * b]     += v * w0;
            acc[2 * b + 1] += v * w1;
        }
    }

#pragma unroll
    for (int k = 0; k < 64; k++) {
        float v = acc[k];
        v += __shfl_down_sync(0xffffffffu, v, 16);
        v += __shfl_down_sync(0xffffffffu, v, 8);
        v += __shfl_down_sync(0xffffffffu, v, 4);
        v += __shfl_down_sync(0xffffffffu, v, 2);
        v += __shfl_down_sync(0xffffffffu, v, 1);
        acc[k] = v;
    }

    __shared__ float sacc[64];
    if (t < 64) sacc[t] = 0.f;
    __syncthreads();
    if ((t & 31) == 0) {
#pragma unroll
        for (int k = 0; k < 64; k++) atomicAdd(&sacc[k], acc[k]);
    }
    __syncthreads();
    if (t < 64) atomicAdd(&g_logits[t], (double)sacc[t]);
}

// ---------------------------------------------------------------------------
// 5) Loss
// ---------------------------------------------------------------------------
__global__ void loss_kernel(const int* __restrict__ y,
                            const float* __restrict__ bf,
                            float* __restrict__ out)
{
    if (threadIdx.x != 0 || blockIdx.x != 0) return;
    double s = 0.0;
    double b0 = (double)bf[0], b1 = (double)bf[1];
    for (int b = 0; b < BATCH; b++) {
        double l0 = g_logits[2 * b]     + b0;
        double l1 = g_logits[2 * b + 1] + b1;
        double m  = l0 > l1 ? l0 : l1;
        double lse = m + log(exp(l0 - m) + exp(l1 - m));
        double lp  = (y[b] == 0 ? l0 : l1) - lse;
        s += lp;
    }
    out[0] = (float)(-s / (double)BATCH);
}

// ---------------------------------------------------------------------------
// Launch
// ---------------------------------------------------------------------------
extern "C" void kernel_launch(void* const* d_in, const int* in_sizes, int n_in,
                              void* d_out, int out_size)
{
    const int*   x     = (const int*)d_in[0];
    const int*   y     = (const int*)d_in[1];
    const float* emb   = (const float*)d_in[2];
    const float* Wq    = (const float*)d_in[3];
    const float* Wkv   = (const float*)d_in[4];
    const float* Wo    = (const float*)d_in[5];
    const float* Wf    = (const float*)d_in[6];
    const float* bf    = (const float*)d_in[7];
    float* out = (float*)d_out;

    __nv_bfloat16 *p_hb, *p_qb, *p_kb, *p_vb, *p_ob, *p_wqkv, *p_wo;
    cudaGetSymbolAddress((void**)&p_hb,   g_hb);
    cudaGetSymbolAddress((void**)&p_qb,   g_qb);
    cudaGetSymbolAddress((void**)&p_kb,   g_kb);
    cudaGetSymbolAddress((void**)&p_vb,   g_vb);
    cudaGetSymbolAddress((void**)&p_ob,   g_ob);
    cudaGetSymbolAddress((void**)&p_wqkv, g_wqkv);
    cudaGetSymbolAddress((void**)&p_wo,   g_wo);

    cudaFuncSetAttribute(gemm_bf16_kernel<false>,
                         cudaFuncAttributeMaxDynamicSharedMemorySize, GEMM_SMEM);
    cudaFuncSetAttribute(gemm_bf16_kernel<true>,
                         cudaFuncAttributeMaxDynamicSharedMemorySize, GEMM_SMEM);
    cudaFuncSetAttribute(attn_kernel,
                         cudaFuncAttributeMaxDynamicSharedMemorySize, ATT_SMEM);

    // 1) gather + weight prep (fused QKV weight buffer)
    gather_kernel<<<ROWS, 256>>>(x, emb);
    dim3 tgrid(32, 32), tblk(256);
    transpose_conv_kernel<<<tgrid, tblk>>>(Wq,  HD,     0,  p_wqkv);
    transpose_conv_kernel<<<tgrid, tblk>>>(Wkv, 2 * HD, 0,  p_wqkv + (size_t)HD * EDIM);
    transpose_conv_kernel<<<tgrid, tblk>>>(Wkv, 2 * HD, HD, p_wqkv + (size_t)2 * HD * EDIM);
    transpose_conv_kernel<<<tgrid, tblk>>>(Wo,  EDIM,   0,  p_wo);

    // 2) fused QKV projection: one GEMM, N = 3072
    dim3 qkvgrid(3 * EDIM / NT, ROWS / MT);  // (24, 512)
    gemm_bf16_kernel<false><<<qkvgrid, 256, GEMM_SMEM>>>(
        p_hb, p_wqkv, nullptr, p_qb, p_kb, p_vb);

    // 3) attention (tensor cores; in place: g_qb <- att)
    attn_kernel<<<LSEQ * NHEAD / ATT_WARPS, 256, ATT_SMEM>>>();

    // 4) out = h + att @ Wo
    dim3 ogrid(EDIM / NT, ROWS / MT);        // (8, 512)
    gemm_bf16_kernel<true><<<ogrid, 256, GEMM_SMEM>>>(
        p_qb, p_wo, p_hb, p_ob, p_ob, p_ob);

    // 5) logits + loss
    zero_logits_kernel<<<1, 64>>>();
    logits_kernel<<<FLAT / 512, 256>>>(Wf);
    loss_kernel<<<1, 32>>>(y, bf, out);
}